// round 3
// baseline (speedup 1.0000x reference)
#include <cuda_runtime.h>
#include <cstdint>
#include <cstddef>

#define NN 30000
#define EE 480000
#define CC 32
#define NTT 15
#define EPSF 1e-8f

// ---------------- scratch (static device globals; no allocation) ----------------
__device__ float g_geo[EE * 9];                 // r, Y1[3], Y2[5] per edge
__device__ float g_m[(size_t)EE * 288];         // messages: [E][9][32] comp-major
__device__ float g_logits[EE * 4];              // per-edge per-head logits
__device__ float g_qn[NN * CC];                 // q projection per node
__device__ float g_f0[2][NN * CC];
__device__ float g_f1[2][NN * CC * 3];          // [N][3][32]
__device__ float g_f2[2][NN * CC * 5];          // [N][5][32]
__device__ int   g_cnt[NN];
__device__ int   g_rowptr[NN + 1];
__device__ int   g_cursor[NN];
__device__ int   g_eid[EE];

#define FULL 0xffffffffu

// ---------------- geometry + degree histogram ----------------
__global__ void __launch_bounds__(256) geo_kernel(const float* __restrict__ pos,
                                                  const int* __restrict__ src,
                                                  const int* __restrict__ dst) {
    int e = blockIdx.x * 256 + threadIdx.x;
    if (e >= EE) return;
    int s = src[e], d = dst[e];
    float rx = pos[d * 3 + 0] - pos[s * 3 + 0];
    float ry = pos[d * 3 + 1] - pos[s * 3 + 1];
    float rz = pos[d * 3 + 2] - pos[s * 3 + 2];
    float r = sqrtf(rx * rx + ry * ry + rz * rz + EPSF);
    float inv = 1.0f / r;
    float x = rx * inv, y = ry * inv, z = rz * inv;
    float* g = &g_geo[e * 9];
    g[0] = r;
    g[1] = x; g[2] = y; g[3] = z;
    g[4] = x * y; g[5] = y * z; g[6] = 3.0f * z * z - 1.0f; g[7] = x * z; g[8] = x * x - y * y;
    atomicAdd(&g_cnt[d], 1);
}

// ---------------- single-block exclusive scan over N counts ----------------
__global__ void __launch_bounds__(1024) scan_kernel() {
    __shared__ int ssum[1024];
    const int CH = 30;                // 1024*30 = 30720 >= 30000
    int t = threadIdx.x;
    int start = t * CH;
    int s = 0;
    for (int i = 0; i < CH; i++) {
        int idx = start + i;
        if (idx < NN) s += g_cnt[idx];
    }
    ssum[t] = s;
    __syncthreads();
    for (int off = 1; off < 1024; off <<= 1) {
        int v = (t >= off) ? ssum[t - off] : 0;
        __syncthreads();
        ssum[t] += v;
        __syncthreads();
    }
    int run = (t == 0) ? 0 : ssum[t - 1];
    for (int i = 0; i < CH; i++) {
        int idx = start + i;
        if (idx < NN) {
            g_rowptr[idx] = run;
            g_cursor[idx] = run;
            run += g_cnt[idx];
        }
    }
    if (t == 0) g_rowptr[NN] = EE;
}

__global__ void __launch_bounds__(256) scatter_kernel(const int* __restrict__ dst) {
    int e = blockIdx.x * 256 + threadIdx.x;
    if (e >= EE) return;
    int p = atomicAdd(&g_cursor[dst[e]], 1);
    g_eid[p] = e;
}

// ---------------- per-node q projection: qn = f0 @ Wq ----------------
__global__ void __launch_bounds__(256) qn_kernel(const float* __restrict__ Wq,
                                                 const float* __restrict__ f0src) {
    __shared__ float sWq[CC * CC];
    int tid = threadIdx.x;
    for (int i = tid; i < CC * CC; i += 256) sWq[i] = Wq[i];
    __syncthreads();
    int lane = tid & 31;
    int n = blockIdx.x * 8 + (tid >> 5);
    float f = f0src[n * CC + lane];
    float q = 0.0f;
#pragma unroll
    for (int c = 0; c < CC; c++)
        q += __shfl_sync(FULL, f, c) * sWq[c * CC + lane];
    g_qn[n * CC + lane] = q;
}

// ---------------- warp-per-edge: radial MLP, messages, logits ----------------
template <bool FIRST>
__global__ void __launch_bounds__(256) edge_kernel(const float* __restrict__ edge_feat,
                                                   const int* __restrict__ src,
                                                   const int* __restrict__ dst,
                                                   const float* __restrict__ Wr1,
                                                   const float* __restrict__ br1,
                                                   const float* __restrict__ Wr2,
                                                   const float* __restrict__ Wk,
                                                   const float* __restrict__ f0src,
                                                   const float* __restrict__ f1src,
                                                   const float* __restrict__ f2src) {
    __shared__ float sWr1[33 * 32];
    __shared__ float sbr1[32];
    __shared__ float sWr2[32 * 224];
    __shared__ float sWk[32 * 32];
    int tid = threadIdx.x;
    for (int i = tid; i < 33 * 32; i += 256) sWr1[i] = Wr1[i];
    if (tid < 32) sbr1[tid] = br1[tid];
    for (int i = tid; i < 32 * 224; i += 256) sWr2[i] = Wr2[i];
    for (int i = tid; i < 32 * 32; i += 256) sWk[i] = Wk[i];
    __syncthreads();

    int wid = tid >> 5, lane = tid & 31;
    int e = blockIdx.x * 8 + wid;
    if (e >= EE) return;
    int s = src[e], d = dst[e];

    float gv = (lane < 9) ? g_geo[e * 9 + lane] : 0.0f;
    float r   = __shfl_sync(FULL, gv, 0);
    float Y10 = __shfl_sync(FULL, gv, 1);
    float Y11 = __shfl_sync(FULL, gv, 2);
    float Y12 = __shfl_sync(FULL, gv, 3);
    float Y20 = __shfl_sync(FULL, gv, 4);
    float Y21 = __shfl_sync(FULL, gv, 5);
    float Y22 = __shfl_sync(FULL, gv, 6);
    float Y23 = __shfl_sync(FULL, gv, 7);
    float Y24 = __shfl_sync(FULL, gv, 8);

    float feat = edge_feat[e * CC + lane];

    // hidden = relu([r, feat] @ Wr1 + br1)
    float h = sbr1[lane] + r * sWr1[lane];
#pragma unroll
    for (int i = 0; i < 32; i++)
        h += __shfl_sync(FULL, feat, i) * sWr1[(i + 1) * 32 + lane];
    h = fmaxf(h, 0.0f);

    // w = hidden @ Wr2 -> 7 values per lane
    float w0 = 0, w1 = 0, w2 = 0, w3 = 0, w4 = 0, w5 = 0, w6 = 0;
#pragma unroll
    for (int i = 0; i < 32; i++) {
        float hv = __shfl_sync(FULL, h, i);
        const float* wr = &sWr2[i * 224 + lane];
        w0 += hv * wr[0];
        w1 += hv * wr[32];
        w2 += hv * wr[64];
        w3 += hv * wr[96];
        w4 += hv * wr[128];
        w5 += hv * wr[160];
        w6 += hv * wr[192];
    }

    // gather source features
    float f0s = f0src[s * CC + lane];
    float f1s0 = 0, f1s1 = 0, f1s2 = 0;
    float f2s0 = 0, f2s1 = 0, f2s2 = 0, f2s3 = 0, f2s4 = 0;
    if (!FIRST) {
        const float* p1 = &f1src[s * 96 + lane];
        f1s0 = p1[0]; f1s1 = p1[32]; f1s2 = p1[64];
        const float* p2 = &f2src[s * 160 + lane];
        f2s0 = p2[0]; f2s1 = p2[32]; f2s2 = p2[64]; f2s3 = p2[96]; f2s4 = p2[128];
    }

    float m0;
    if (FIRST) {
        m0 = w0 * f0s;
    } else {
        float dot1 = f1s0 * Y10 + f1s1 * Y11 + f1s2 * Y12;
        float dot2 = f2s0 * Y20 + f2s1 * Y21 + f2s2 * Y22 + f2s3 * Y23 + f2s4 * Y24;
        m0 = w0 * f0s + w1 * dot1 + w2 * dot2;
    }
    float m10 = w3 * f0s * Y10 + w4 * f1s0;
    float m11 = w3 * f0s * Y11 + w4 * f1s1;
    float m12 = w3 * f0s * Y12 + w4 * f1s2;
    float m20 = w5 * f0s * Y20 + w6 * f2s0;
    float m21 = w5 * f0s * Y21 + w6 * f2s1;
    float m22 = w5 * f0s * Y22 + w6 * f2s2;
    float m23 = w5 * f0s * Y23 + w6 * f2s3;
    float m24 = w5 * f0s * Y24 + w6 * f2s4;

    float* mb = &g_m[(size_t)e * 288];
    mb[lane]         = m0;
    mb[32 + lane]    = m10;
    mb[64 + lane]    = m11;
    mb[96 + lane]    = m12;
    mb[128 + lane]   = m20;
    mb[160 + lane]   = m21;
    mb[192 + lane]   = m22;
    mb[224 + lane]   = m23;
    mb[256 + lane]   = m24;

    // k = m0 @ Wk ; logits = sum over head-dim of q*k / sqrt(8)
    float kk = 0.0f;
#pragma unroll
    for (int c = 0; c < 32; c++)
        kk += __shfl_sync(FULL, m0, c) * sWk[c * 32 + lane];
    float qv = g_qn[d * CC + lane];
    float p = qv * kk;
    p += __shfl_xor_sync(FULL, p, 1);
    p += __shfl_xor_sync(FULL, p, 2);
    p += __shfl_xor_sync(FULL, p, 4);
    if ((lane & 7) == 0)
        g_logits[e * 4 + (lane >> 3)] = p * 0.35355339059327373f;
}

// ---------------- warp-per-node: softmax + aggregate + self-interaction ----------------
__global__ void __launch_bounds__(256) agg_kernel(const float* __restrict__ Ws0,
                                                  const float* __restrict__ Ws1,
                                                  const float* __restrict__ Ws2,
                                                  const float* __restrict__ Wsk,
                                                  const float* __restrict__ f0old,
                                                  float* __restrict__ f0out,
                                                  float* __restrict__ f1out,
                                                  float* __restrict__ f2out) {
    __shared__ float sW0[1024], sW1[1024], sW2[1024], sWkm[1024];
    __shared__ float sAcc[8][320];
    int tid = threadIdx.x;
    for (int i = tid; i < 1024; i += 256) {
        sW0[i] = Ws0[i]; sW1[i] = Ws1[i]; sW2[i] = Ws2[i]; sWkm[i] = Wsk[i];
    }
    __syncthreads();

    int wid = tid >> 5, lane = tid & 31;
    int n = blockIdx.x * 8 + wid;
    int beg = g_rowptr[n], end = g_rowptr[n + 1];
    int deg = end - beg;

    // per-head max
    float mx0 = -1e30f, mx1 = -1e30f, mx2 = -1e30f, mx3 = -1e30f;
    for (int j = lane; j < deg; j += 32) {
        int e = g_eid[beg + j];
        float4 lg = *(const float4*)&g_logits[e * 4];
        mx0 = fmaxf(mx0, lg.x); mx1 = fmaxf(mx1, lg.y);
        mx2 = fmaxf(mx2, lg.z); mx3 = fmaxf(mx3, lg.w);
    }
#pragma unroll
    for (int o = 16; o > 0; o >>= 1) {
        mx0 = fmaxf(mx0, __shfl_xor_sync(FULL, mx0, o));
        mx1 = fmaxf(mx1, __shfl_xor_sync(FULL, mx1, o));
        mx2 = fmaxf(mx2, __shfl_xor_sync(FULL, mx2, o));
        mx3 = fmaxf(mx3, __shfl_xor_sync(FULL, mx3, o));
    }
    // per-head denominator
    float d0 = 0, d1 = 0, d2 = 0, d3 = 0;
    for (int j = lane; j < deg; j += 32) {
        int e = g_eid[beg + j];
        float4 lg = *(const float4*)&g_logits[e * 4];
        d0 += expf(lg.x - mx0); d1 += expf(lg.y - mx1);
        d2 += expf(lg.z - mx2); d3 += expf(lg.w - mx3);
    }
#pragma unroll
    for (int o = 16; o > 0; o >>= 1) {
        d0 += __shfl_xor_sync(FULL, d0, o);
        d1 += __shfl_xor_sync(FULL, d1, o);
        d2 += __shfl_xor_sync(FULL, d2, o);
        d3 += __shfl_xor_sync(FULL, d3, o);
    }
    int h = lane >> 3;
    float mxh  = (h == 0) ? mx0 : (h == 1) ? mx1 : (h == 2) ? mx2 : mx3;
    float invh = 1.0f / (((h == 0) ? d0 : (h == 1) ? d1 : (h == 2) ? d2 : d3) + EPSF);

    float a0 = 0, a10 = 0, a11 = 0, a12 = 0;
    float a20 = 0, a21 = 0, a22 = 0, a23 = 0, a24 = 0;
    for (int j = 0; j < deg; j++) {
        int e = g_eid[beg + j];
        float al = expf(g_logits[e * 4 + h] - mxh) * invh;
        const float* mb = &g_m[(size_t)e * 288];
        a0  += al * mb[lane];
        a10 += al * mb[32 + lane];
        a11 += al * mb[64 + lane];
        a12 += al * mb[96 + lane];
        a20 += al * mb[128 + lane];
        a21 += al * mb[160 + lane];
        a22 += al * mb[192 + lane];
        a23 += al * mb[224 + lane];
        a24 += al * mb[256 + lane];
    }

    float* sa = sAcc[wid];
    sa[lane]        = a0;
    sa[32 + lane]   = a10;
    sa[64 + lane]   = a11;
    sa[96 + lane]   = a12;
    sa[128 + lane]  = a20;
    sa[160 + lane]  = a21;
    sa[192 + lane]  = a22;
    sa[224 + lane]  = a23;
    sa[256 + lane]  = a24;
    sa[288 + lane]  = f0old[n * CC + lane];
    __syncwarp();

    float o0 = 0, o10 = 0, o11 = 0, o12 = 0;
    float o20 = 0, o21 = 0, o22 = 0, o23 = 0, o24 = 0;
#pragma unroll
    for (int c = 0; c < 32; c++) {
        float w0v = sW0[c * 32 + lane], wkv = sWkm[c * 32 + lane];
        float w1v = sW1[c * 32 + lane], w2v = sW2[c * 32 + lane];
        o0  += sa[c] * w0v + sa[288 + c] * wkv;
        o10 += sa[32 + c] * w1v;
        o11 += sa[64 + c] * w1v;
        o12 += sa[96 + c] * w1v;
        o20 += sa[128 + c] * w2v;
        o21 += sa[160 + c] * w2v;
        o22 += sa[192 + c] * w2v;
        o23 += sa[224 + c] * w2v;
        o24 += sa[256 + c] * w2v;
    }
    f0out[n * CC + lane] = o0;
    f1out[n * 96 + lane]       = o10;
    f1out[n * 96 + 32 + lane]  = o11;
    f1out[n * 96 + 64 + lane]  = o12;
    f2out[n * 160 + lane]        = o20;
    f2out[n * 160 + 32 + lane]   = o21;
    f2out[n * 160 + 64 + lane]   = o22;
    f2out[n * 160 + 96 + lane]   = o23;
    f2out[n * 160 + 128 + lane]  = o24;
}

// ---------------- final projection: hs0 = f0 @ Wout ; cs = hs0 @ Wc ----------------
__global__ void __launch_bounds__(256) out_kernel(const float* __restrict__ Wout,
                                                  const float* __restrict__ Wc,
                                                  const float* __restrict__ f0,
                                                  float* __restrict__ out) {
    __shared__ float sWo[1024];
    __shared__ float sWc[32 * NTT];
    int tid = threadIdx.x;
    for (int i = tid; i < 1024; i += 256) sWo[i] = Wout[i];
    for (int i = tid; i < 32 * NTT; i += 256) sWc[i] = Wc[i];
    __syncthreads();
    int lane = tid & 31;
    int n = blockIdx.x * 8 + (tid >> 5);
    float f = f0[n * CC + lane];
    float hs = 0.0f;
#pragma unroll
    for (int c = 0; c < 32; c++)
        hs += __shfl_sync(FULL, f, c) * sWo[c * 32 + lane];
    out[n * CC + lane] = hs;
    float cs = 0.0f;
#pragma unroll
    for (int c = 0; c < 32; c++) {
        float hv = __shfl_sync(FULL, hs, c);
        float wc = (lane < NTT) ? sWc[c * NTT + lane] : 0.0f;
        cs += hv * wc;
    }
    if (lane < NTT) out[NN * CC + n * NTT + lane] = cs;
}

// ---------------- host ----------------
extern "C" void kernel_launch(void* const* d_in, const int* in_sizes, int n_in,
                              void* d_out, int out_size) {
    const float* pos       = (const float*)d_in[0];
    const float* node_l0   = (const float*)d_in[1];
    const float* edge_feat = (const float*)d_in[2];
    const int*   edge_src  = (const int*)d_in[3];
    const int*   edge_dst  = (const int*)d_in[4];
    const float* Wr1       = (const float*)d_in[5];
    const float* br1       = (const float*)d_in[6];
    const float* Wr2       = (const float*)d_in[7];
    const float* Wq        = (const float*)d_in[8];
    const float* Wk        = (const float*)d_in[9];
    const float* Ws0       = (const float*)d_in[10];
    const float* Ws1       = (const float*)d_in[11];
    const float* Ws2       = (const float*)d_in[12];
    const float* Wsk       = (const float*)d_in[13];
    const float* Wout      = (const float*)d_in[14];
    const float* Wc        = (const float*)d_in[15];
    float* out = (float*)d_out;

    void *pcnt, *pf0, *pf1, *pf2;
    cudaGetSymbolAddress(&pcnt, g_cnt);
    cudaGetSymbolAddress(&pf0, g_f0);
    cudaGetSymbolAddress(&pf1, g_f1);
    cudaGetSymbolAddress(&pf2, g_f2);
    float* f0a = (float*)pf0;
    float* f0b = f0a + (size_t)NN * CC;
    float* f1a = (float*)pf1;
    float* f1b = f1a + (size_t)NN * CC * 3;
    float* f2a = (float*)pf2;
    float* f2b = f2a + (size_t)NN * CC * 5;

    cudaMemsetAsync(pcnt, 0, NN * sizeof(int));
    geo_kernel<<<EE / 256, 256>>>(pos, edge_src, edge_dst);
    scan_kernel<<<1, 1024>>>();
    scatter_kernel<<<EE / 256, 256>>>(edge_dst);

    // ---- layer 0 (f1 = f2 = 0) ----
    qn_kernel<<<NN / 8, 256>>>(Wq, node_l0);
    edge_kernel<true><<<EE / 8, 256>>>(edge_feat, edge_src, edge_dst,
                                       Wr1, br1, Wr2, Wk,
                                       node_l0, nullptr, nullptr);
    agg_kernel<<<NN / 8, 256>>>(Ws0, Ws1, Ws2, Wsk, node_l0, f0a, f1a, f2a);

    // ---- layer 1 ----
    qn_kernel<<<NN / 8, 256>>>(Wq + 1024, f0a);
    edge_kernel<false><<<EE / 8, 256>>>(edge_feat, edge_src, edge_dst,
                                        Wr1 + 33 * 32, br1 + 32, Wr2 + 32 * 224, Wk + 1024,
                                        f0a, f1a, f2a);
    agg_kernel<<<NN / 8, 256>>>(Ws0 + 1024, Ws1 + 1024, Ws2 + 1024, Wsk + 1024,
                                f0a, f0b, f1b, f2b);

    out_kernel<<<NN / 8, 256>>>(Wout, Wc, f0b, out);
}

// round 4
// speedup vs baseline: 1.9705x; 1.9705x over previous
#include <cuda_runtime.h>
#include <cstdint>
#include <cstddef>

#define NN 30000
#define EE 480000
#define CC 32
#define NTT 15
#define EPSF 1e-8f

// ---------------- scratch (static device globals; no allocation) ----------------
__device__ float g_geo[(size_t)EE * 12];        // r, Y1[3], Y2[5], pad[3]
__device__ float g_blk[(size_t)EE * 160];       // per edge: m0, a1=w3*f0s, w4, a2=w5*f0s, w6  (5 x 32)
__device__ float g_logits[EE * 4];
__device__ float g_v[(size_t)NN * 128];         // permuted per-node attention vectors
__device__ float g_f0[2][NN * CC];
__device__ float g_f1[2][NN * CC * 3];
__device__ float g_f2[2][NN * CC * 5];
__device__ int   g_cnt[NN];
__device__ int   g_rowptr[NN + 1];
__device__ int   g_cursor[NN];
__device__ int   g_eid[EE];

#define FULL 0xffffffffu

// ---------------- f32x2 packed helpers ----------------
__device__ __forceinline__ unsigned long long pk2(float lo, float hi) {
    unsigned long long r;
    asm("mov.b64 %0, {%1, %2};" : "=l"(r) : "f"(lo), "f"(hi));
    return r;
}
__device__ __forceinline__ void unpk(unsigned long long v, float& lo, float& hi) {
    asm("mov.b64 {%0, %1}, %2;" : "=f"(lo), "=f"(hi) : "l"(v));
}
__device__ __forceinline__ unsigned long long dup2(float v) {
    unsigned long long r;
    asm("mov.b64 %0, {%1, %1};" : "=l"(r) : "f"(v));
    return r;
}
__device__ __forceinline__ unsigned long long fma2(unsigned long long a, unsigned long long b,
                                                   unsigned long long c) {
    unsigned long long d;
    asm("fma.rn.f32x2 %0, %1, %2, %3;" : "=l"(d) : "l"(a), "l"(b), "l"(c));
    return d;
}

// ---------------- geometry + degree histogram ----------------
__global__ void __launch_bounds__(256) geo_kernel(const float* __restrict__ pos,
                                                  const int* __restrict__ src,
                                                  const int* __restrict__ dst) {
    int e = blockIdx.x * 256 + threadIdx.x;
    if (e >= EE) return;
    int s = src[e], d = dst[e];
    float rx = pos[d * 3 + 0] - pos[s * 3 + 0];
    float ry = pos[d * 3 + 1] - pos[s * 3 + 1];
    float rz = pos[d * 3 + 2] - pos[s * 3 + 2];
    float r = sqrtf(rx * rx + ry * ry + rz * rz + EPSF);
    float inv = 1.0f / r;
    float x = rx * inv, y = ry * inv, z = rz * inv;
    float4* gp = (float4*)&g_geo[(size_t)e * 12];
    gp[0] = make_float4(r, x, y, z);
    gp[1] = make_float4(x * y, y * z, 3.0f * z * z - 1.0f, x * z);
    gp[2] = make_float4(x * x - y * y, 0.0f, 0.0f, 0.0f);
    atomicAdd(&g_cnt[d], 1);
}

// ---------------- single-block exclusive scan over N counts ----------------
__global__ void __launch_bounds__(1024) scan_kernel() {
    __shared__ int ssum[1024];
    const int CH = 30;
    int t = threadIdx.x;
    int start = t * CH;
    int s = 0;
    for (int i = 0; i < CH; i++) {
        int idx = start + i;
        if (idx < NN) s += g_cnt[idx];
    }
    ssum[t] = s;
    __syncthreads();
    for (int off = 1; off < 1024; off <<= 1) {
        int v = (t >= off) ? ssum[t - off] : 0;
        __syncthreads();
        ssum[t] += v;
        __syncthreads();
    }
    int run = (t == 0) ? 0 : ssum[t - 1];
    for (int i = 0; i < CH; i++) {
        int idx = start + i;
        if (idx < NN) {
            g_rowptr[idx] = run;
            g_cursor[idx] = run;
            run += g_cnt[idx];
        }
    }
    if (t == 0) g_rowptr[NN] = EE;
}

__global__ void __launch_bounds__(256) scatter_kernel(const int* __restrict__ dst) {
    int e = blockIdx.x * 256 + threadIdx.x;
    if (e >= EE) return;
    int p = atomicAdd(&g_cursor[dst[e]], 1);
    g_eid[p] = e;
}

// ---------------- per-node attention vectors ----------------
// q = f0 @ Wq (scaled by 1/sqrt(8)); v_h[c'] = sum_{dh} q[h*8+dh] * Wk[c'][h*8+dh]
// stored permuted: g_v[n*128 + k*32 + lane] = v[lane>>3][(lane&7) + 8k]
__global__ void __launch_bounds__(256) vn_kernel(const float* __restrict__ Wq,
                                                 const float* __restrict__ Wk,
                                                 const float* __restrict__ f0src) {
    __shared__ float sWq[1024];
    __shared__ float sWkT[1024];   // sWkT[j*32 + c'] = Wk[c'][j]
    int tid = threadIdx.x;
    for (int i = tid; i < 1024; i += 256) {
        sWq[i] = Wq[i];
        sWkT[i] = Wk[(i & 31) * 32 + (i >> 5)];
    }
    __syncthreads();
    int lane = tid & 31;
    int n = blockIdx.x * 8 + (tid >> 5);
    float f = f0src[n * CC + lane];
    float q = 0.0f;
#pragma unroll
    for (int c = 0; c < CC; c++)
        q = fmaf(__shfl_sync(FULL, f, c), sWq[c * 32 + lane], q);
    q *= 0.35355339059327373f;     // fold 1/sqrt(Dh)

    float v0 = 0, v1 = 0, v2 = 0, v3 = 0;
#pragma unroll
    for (int dh = 0; dh < 8; dh++) {
        v0 = fmaf(__shfl_sync(FULL, q, dh),      sWkT[dh * 32 + lane],        v0);
        v1 = fmaf(__shfl_sync(FULL, q, 8 + dh),  sWkT[(8 + dh) * 32 + lane],  v1);
        v2 = fmaf(__shfl_sync(FULL, q, 16 + dh), sWkT[(16 + dh) * 32 + lane], v2);
        v3 = fmaf(__shfl_sync(FULL, q, 24 + dh), sWkT[(24 + dh) * 32 + lane], v3);
    }
    int hh = lane >> 3;
#pragma unroll
    for (int k = 0; k < 4; k++) {
        int sl = (lane & 7) + 8 * k;
        float t0 = __shfl_sync(FULL, v0, sl);
        float t1 = __shfl_sync(FULL, v1, sl);
        float t2 = __shfl_sync(FULL, v2, sl);
        float t3 = __shfl_sync(FULL, v3, sl);
        float val = (hh == 0) ? t0 : (hh == 1) ? t1 : (hh == 2) ? t2 : t3;
        g_v[(size_t)n * 128 + k * 32 + lane] = val;
    }
}

// ---------------- edge kernel: 4 edges per warp, f32x2 radial MLP ----------------
template <bool FIRST>
__global__ void __launch_bounds__(256) edge_kernel(const float* __restrict__ edge_feat,
                                                   const int* __restrict__ src,
                                                   const int* __restrict__ dst,
                                                   const float* __restrict__ Wr1,
                                                   const float* __restrict__ br1,
                                                   const float* __restrict__ Wr2,
                                                   const float* __restrict__ f0src,
                                                   const float* __restrict__ f1src,
                                                   const float* __restrict__ f2src) {
    __shared__ float sWr1[33 * 32];
    __shared__ float sbr1[32];
    __shared__ float sWr2[32 * 224];
    int tid = threadIdx.x;
    for (int i = tid; i < 33 * 32; i += 256) sWr1[i] = Wr1[i];
    if (tid < 32) sbr1[tid] = br1[tid];
    for (int i = tid; i < 32 * 224; i += 256) sWr2[i] = Wr2[i];
    __syncthreads();

    int wid = tid >> 5, lane = tid & 31;
    int wstride = gridDim.x * 8;

    for (int g = blockIdx.x * 8 + wid; g < EE / 4; g += wstride) {
        int e4 = g * 4;

        // ---- gather per-edge scalars ----
        float feat0 = edge_feat[(size_t)(e4 + 0) * CC + lane];
        float feat1 = edge_feat[(size_t)(e4 + 1) * CC + lane];
        float feat2 = edge_feat[(size_t)(e4 + 2) * CC + lane];
        float feat3 = edge_feat[(size_t)(e4 + 3) * CC + lane];
        unsigned long long fp01 = pk2(feat0, feat1);
        unsigned long long fp23 = pk2(feat2, feat3);
        float r0 = g_geo[(size_t)(e4 + 0) * 12];
        float r1 = g_geo[(size_t)(e4 + 1) * 12];
        float r2 = g_geo[(size_t)(e4 + 2) * 12];
        float r3 = g_geo[(size_t)(e4 + 3) * 12];

        // ---- hidden = relu([r,feat] @ Wr1 + b) for 4 edges, f32x2 pairs ----
        float hb = sbr1[lane];
        float w0l = sWr1[lane];
        unsigned long long h01 = pk2(fmaf(r0, w0l, hb), fmaf(r1, w0l, hb));
        unsigned long long h23 = pk2(fmaf(r2, w0l, hb), fmaf(r3, w0l, hb));
#pragma unroll
        for (int i = 0; i < 32; i++) {
            unsigned long long wd = dup2(sWr1[(i + 1) * 32 + lane]);
            unsigned long long f01 = __shfl_sync(FULL, fp01, i);
            unsigned long long f23 = __shfl_sync(FULL, fp23, i);
            h01 = fma2(f01, wd, h01);
            h23 = fma2(f23, wd, h23);
        }
        {
            float a, b;
            unpk(h01, a, b); h01 = pk2(fmaxf(a, 0.f), fmaxf(b, 0.f));
            unpk(h23, a, b); h23 = pk2(fmaxf(a, 0.f), fmaxf(b, 0.f));
        }

        // ---- w = hidden @ Wr2 : 7 outputs/lane, 4 edges packed in two f32x2 sets ----
        unsigned long long W01[7], W23[7];
#pragma unroll
        for (int p = 0; p < 7; p++) { W01[p] = 0ull; W23[p] = 0ull; }
#pragma unroll
        for (int i = 0; i < 32; i++) {
            unsigned long long hs01 = __shfl_sync(FULL, h01, i);
            unsigned long long hs23 = __shfl_sync(FULL, h23, i);
            const float* wr = &sWr2[i * 224 + lane];
#pragma unroll
            for (int p = 0; p < 7; p++) {
                unsigned long long wd = dup2(wr[p * 32]);
                W01[p] = fma2(hs01, wd, W01[p]);
                W23[p] = fma2(hs23, wd, W23[p]);
            }
        }

        // ---- per-edge message + logits ----
#pragma unroll
        for (int pe = 0; pe < 4; pe++) {
            float wv[7];
#pragma unroll
            for (int p = 0; p < 7; p++) {
                float lo, hi;
                unpk((pe < 2) ? W01[p] : W23[p], lo, hi);
                wv[p] = (pe & 1) ? hi : lo;
            }
            int e = e4 + pe;
            int s = src[e];
            int d = dst[e];
            float f0s = f0src[(size_t)s * CC + lane];
            float m0;
            if (FIRST) {
                m0 = wv[0] * f0s;
            } else {
                const float4 ga = *(const float4*)&g_geo[(size_t)e * 12];      // r,Y10,Y11,Y12
                const float4 gb = *(const float4*)&g_geo[(size_t)e * 12 + 4];  // Y20..Y23
                float Y24 = g_geo[(size_t)e * 12 + 8];
                const float* p1 = &f1src[(size_t)s * 96 + lane];
                float f1a = p1[0], f1b = p1[32], f1c = p1[64];
                const float* p2 = &f2src[(size_t)s * 160 + lane];
                float f2a = p2[0], f2b = p2[32], f2c = p2[64], f2d = p2[96], f2e = p2[128];
                float dot1 = f1a * ga.y + f1b * ga.z + f1c * ga.w;
                float dot2 = f2a * gb.x + f2b * gb.y + f2c * gb.z + f2d * gb.w + f2e * Y24;
                m0 = wv[0] * f0s + wv[1] * dot1 + wv[2] * dot2;
            }
            float* blk = &g_blk[(size_t)e * 160];
            blk[lane]       = m0;
            blk[32 + lane]  = wv[3] * f0s;
            blk[96 + lane]  = wv[5] * f0s;
            if (!FIRST) {
                blk[64 + lane]  = wv[4];
                blk[128 + lane] = wv[6];
            }
            // logits: each 8-lane group handles one head
            float acc = 0.0f;
#pragma unroll
            for (int k = 0; k < 4; k++) {
                float mv = __shfl_sync(FULL, m0, (lane & 7) + 8 * k);
                acc = fmaf(mv, __ldg(&g_v[(size_t)d * 128 + k * 32 + lane]), acc);
            }
            acc += __shfl_xor_sync(FULL, acc, 4);
            acc += __shfl_xor_sync(FULL, acc, 2);
            acc += __shfl_xor_sync(FULL, acc, 1);
            if ((lane & 7) == 0) g_logits[e * 4 + (lane >> 3)] = acc;
        }
    }
}

// ---------------- warp-per-node: softmax + aggregate (recompute m1/m2) + self-mix ----------------
template <bool FIRST>
__global__ void __launch_bounds__(256) agg_kernel(const float* __restrict__ Ws0,
                                                  const float* __restrict__ Ws1,
                                                  const float* __restrict__ Ws2,
                                                  const float* __restrict__ Wsk,
                                                  const int* __restrict__ srcArr,
                                                  const float* __restrict__ f1src,
                                                  const float* __restrict__ f2src,
                                                  const float* __restrict__ f0old,
                                                  float* __restrict__ f0out,
                                                  float* __restrict__ f1out,
                                                  float* __restrict__ f2out) {
    __shared__ float sW0[1024], sW1[1024], sW2[1024], sWkm[1024];
    __shared__ float sAcc[8][320];
    int tid = threadIdx.x;
    for (int i = tid; i < 1024; i += 256) {
        sW0[i] = Ws0[i]; sW1[i] = Ws1[i]; sW2[i] = Ws2[i]; sWkm[i] = Wsk[i];
    }
    __syncthreads();

    int wid = tid >> 5, lane = tid & 31;
    int n = blockIdx.x * 8 + wid;
    int beg = g_rowptr[n], end = g_rowptr[n + 1];
    int deg = end - beg;

    float mx0 = -1e30f, mx1 = -1e30f, mx2 = -1e30f, mx3 = -1e30f;
    for (int j = lane; j < deg; j += 32) {
        int e = g_eid[beg + j];
        float4 lg = *(const float4*)&g_logits[e * 4];
        mx0 = fmaxf(mx0, lg.x); mx1 = fmaxf(mx1, lg.y);
        mx2 = fmaxf(mx2, lg.z); mx3 = fmaxf(mx3, lg.w);
    }
#pragma unroll
    for (int o = 16; o > 0; o >>= 1) {
        mx0 = fmaxf(mx0, __shfl_xor_sync(FULL, mx0, o));
        mx1 = fmaxf(mx1, __shfl_xor_sync(FULL, mx1, o));
        mx2 = fmaxf(mx2, __shfl_xor_sync(FULL, mx2, o));
        mx3 = fmaxf(mx3, __shfl_xor_sync(FULL, mx3, o));
    }
    float d0 = 0, d1 = 0, d2 = 0, d3 = 0;
    for (int j = lane; j < deg; j += 32) {
        int e = g_eid[beg + j];
        float4 lg = *(const float4*)&g_logits[e * 4];
        d0 += expf(lg.x - mx0); d1 += expf(lg.y - mx1);
        d2 += expf(lg.z - mx2); d3 += expf(lg.w - mx3);
    }
#pragma unroll
    for (int o = 16; o > 0; o >>= 1) {
        d0 += __shfl_xor_sync(FULL, d0, o);
        d1 += __shfl_xor_sync(FULL, d1, o);
        d2 += __shfl_xor_sync(FULL, d2, o);
        d3 += __shfl_xor_sync(FULL, d3, o);
    }
    int h = lane >> 3;
    float mxh  = (h == 0) ? mx0 : (h == 1) ? mx1 : (h == 2) ? mx2 : mx3;
    float invh = 1.0f / (((h == 0) ? d0 : (h == 1) ? d1 : (h == 2) ? d2 : d3) + EPSF);

    float A0 = 0, A10 = 0, A11 = 0, A12 = 0;
    float A20 = 0, A21 = 0, A22 = 0, A23 = 0, A24 = 0;
#pragma unroll 2
    for (int j = 0; j < deg; j++) {
        int e = g_eid[beg + j];
        float al = expf(g_logits[e * 4 + h] - mxh) * invh;
        const float* blk = &g_blk[(size_t)e * 160];
        float m0 = blk[lane];
        float a1 = blk[32 + lane];
        float a2 = blk[96 + lane];
        const float4 ga = __ldg((const float4*)&g_geo[(size_t)e * 12]);
        const float4 gb = __ldg((const float4*)&g_geo[(size_t)e * 12 + 4]);
        float Y24 = __ldg(&g_geo[(size_t)e * 12 + 8]);
        A0 = fmaf(al, m0, A0);
        float t1 = al * a1, t2 = al * a2;
        A10 = fmaf(t1, ga.y, A10); A11 = fmaf(t1, ga.z, A11); A12 = fmaf(t1, ga.w, A12);
        A20 = fmaf(t2, gb.x, A20); A21 = fmaf(t2, gb.y, A21);
        A22 = fmaf(t2, gb.z, A22); A23 = fmaf(t2, gb.w, A23); A24 = fmaf(t2, Y24, A24);
        if (!FIRST) {
            float t4 = al * blk[64 + lane];
            float t6 = al * blk[128 + lane];
            int s = __ldg(&srcArr[e]);
            const float* p1 = &f1src[(size_t)s * 96 + lane];
            A10 = fmaf(t4, p1[0], A10); A11 = fmaf(t4, p1[32], A11); A12 = fmaf(t4, p1[64], A12);
            const float* p2 = &f2src[(size_t)s * 160 + lane];
            A20 = fmaf(t6, p2[0], A20);  A21 = fmaf(t6, p2[32], A21);
            A22 = fmaf(t6, p2[64], A22); A23 = fmaf(t6, p2[96], A23); A24 = fmaf(t6, p2[128], A24);
        }
    }

    float* sa = sAcc[wid];
    sa[lane]        = A0;
    sa[32 + lane]   = A10;
    sa[64 + lane]   = A11;
    sa[96 + lane]   = A12;
    sa[128 + lane]  = A20;
    sa[160 + lane]  = A21;
    sa[192 + lane]  = A22;
    sa[224 + lane]  = A23;
    sa[256 + lane]  = A24;
    sa[288 + lane]  = f0old[n * CC + lane];
    __syncwarp();

    float o0 = 0, o10 = 0, o11 = 0, o12 = 0;
    float o20 = 0, o21 = 0, o22 = 0, o23 = 0, o24 = 0;
#pragma unroll
    for (int c = 0; c < 32; c++) {
        float w0v = sW0[c * 32 + lane], wkv = sWkm[c * 32 + lane];
        float w1v = sW1[c * 32 + lane], w2v = sW2[c * 32 + lane];
        o0  = fmaf(sa[c], w0v, fmaf(sa[288 + c], wkv, o0));
        o10 = fmaf(sa[32 + c],  w1v, o10);
        o11 = fmaf(sa[64 + c],  w1v, o11);
        o12 = fmaf(sa[96 + c],  w1v, o12);
        o20 = fmaf(sa[128 + c], w2v, o20);
        o21 = fmaf(sa[160 + c], w2v, o21);
        o22 = fmaf(sa[192 + c], w2v, o22);
        o23 = fmaf(sa[224 + c], w2v, o23);
        o24 = fmaf(sa[256 + c], w2v, o24);
    }
    f0out[n * CC + lane] = o0;
    f1out[n * 96 + lane]       = o10;
    f1out[n * 96 + 32 + lane]  = o11;
    f1out[n * 96 + 64 + lane]  = o12;
    f2out[n * 160 + lane]        = o20;
    f2out[n * 160 + 32 + lane]   = o21;
    f2out[n * 160 + 64 + lane]   = o22;
    f2out[n * 160 + 96 + lane]   = o23;
    f2out[n * 160 + 128 + lane]  = o24;
}

// ---------------- final projection ----------------
__global__ void __launch_bounds__(256) out_kernel(const float* __restrict__ Wout,
                                                  const float* __restrict__ Wc,
                                                  const float* __restrict__ f0,
                                                  float* __restrict__ out) {
    __shared__ float sWo[1024];
    __shared__ float sWc[32 * NTT];
    int tid = threadIdx.x;
    for (int i = tid; i < 1024; i += 256) sWo[i] = Wout[i];
    for (int i = tid; i < 32 * NTT; i += 256) sWc[i] = Wc[i];
    __syncthreads();
    int lane = tid & 31;
    int n = blockIdx.x * 8 + (tid >> 5);
    float f = f0[n * CC + lane];
    float hs = 0.0f;
#pragma unroll
    for (int c = 0; c < 32; c++)
        hs = fmaf(__shfl_sync(FULL, f, c), sWo[c * 32 + lane], hs);
    out[n * CC + lane] = hs;
    float cs = 0.0f;
#pragma unroll
    for (int c = 0; c < 32; c++) {
        float hv = __shfl_sync(FULL, hs, c);
        float wc = (lane < NTT) ? sWc[c * NTT + lane] : 0.0f;
        cs = fmaf(hv, wc, cs);
    }
    if (lane < NTT) out[NN * CC + n * NTT + lane] = cs;
}

// ---------------- host ----------------
extern "C" void kernel_launch(void* const* d_in, const int* in_sizes, int n_in,
                              void* d_out, int out_size) {
    const float* pos       = (const float*)d_in[0];
    const float* node_l0   = (const float*)d_in[1];
    const float* edge_feat = (const float*)d_in[2];
    const int*   edge_src  = (const int*)d_in[3];
    const int*   edge_dst  = (const int*)d_in[4];
    const float* Wr1       = (const float*)d_in[5];
    const float* br1       = (const float*)d_in[6];
    const float* Wr2       = (const float*)d_in[7];
    const float* Wq        = (const float*)d_in[8];
    const float* Wk        = (const float*)d_in[9];
    const float* Ws0       = (const float*)d_in[10];
    const float* Ws1       = (const float*)d_in[11];
    const float* Ws2       = (const float*)d_in[12];
    const float* Wsk       = (const float*)d_in[13];
    const float* Wout      = (const float*)d_in[14];
    const float* Wc        = (const float*)d_in[15];
    float* out = (float*)d_out;

    void *pcnt, *pf0, *pf1, *pf2;
    cudaGetSymbolAddress(&pcnt, g_cnt);
    cudaGetSymbolAddress(&pf0, g_f0);
    cudaGetSymbolAddress(&pf1, g_f1);
    cudaGetSymbolAddress(&pf2, g_f2);
    float* f0a = (float*)pf0;
    float* f0b = f0a + (size_t)NN * CC;
    float* f1a = (float*)pf1;
    float* f1b = f1a + (size_t)NN * CC * 3;
    float* f2a = (float*)pf2;
    float* f2b = f2a + (size_t)NN * CC * 5;

    cudaMemsetAsync(pcnt, 0, NN * sizeof(int));
    geo_kernel<<<EE / 256, 256>>>(pos, edge_src, edge_dst);
    scan_kernel<<<1, 1024>>>();
    scatter_kernel<<<EE / 256, 256>>>(edge_dst);

    const int EGRID = 1875;   // grid-stride; 8 warps/block x 4 edges/warp

    // ---- layer 0 (f1 = f2 = 0) ----
    vn_kernel<<<NN / 8, 256>>>(Wq, Wk, node_l0);
    edge_kernel<true><<<EGRID, 256>>>(edge_feat, edge_src, edge_dst,
                                      Wr1, br1, Wr2, node_l0, nullptr, nullptr);
    agg_kernel<true><<<NN / 8, 256>>>(Ws0, Ws1, Ws2, Wsk, edge_src,
                                      nullptr, nullptr, node_l0, f0a, f1a, f2a);

    // ---- layer 1 ----
    vn_kernel<<<NN / 8, 256>>>(Wq + 1024, Wk + 1024, f0a);
    edge_kernel<false><<<EGRID, 256>>>(edge_feat, edge_src, edge_dst,
                                       Wr1 + 33 * 32, br1 + 32, Wr2 + 32 * 224,
                                       f0a, f1a, f2a);
    agg_kernel<false><<<NN / 8, 256>>>(Ws0 + 1024, Ws1 + 1024, Ws2 + 1024, Wsk + 1024,
                                       edge_src, f1a, f2a, f0a, f0b, f1b, f2b);

    out_kernel<<<NN / 8, 256>>>(Wout, Wc, f0b, out);
}